// round 2
// baseline (speedup 1.0000x reference)
#include <cuda_runtime.h>
#include <cstdint>
#include <cstddef>

// Problem constants
#define BATCH   16384
#define HDIM    512
#define ODIM    128
#define NEXP    5
#define NBANK   3
#define NZ      15          // NBANK * NEXP

// Tiling
#define BM 128
#define BN 128
#define BK 16
#define NTHREADS 256

// Scratch for intermediate H = relu(X@W1+b1): [15, 16384, 512] fp32
__device__ float g_H[(size_t)NZ * BATCH * HDIM];

// ---------------------------------------------------------------------------
// helpers
// ---------------------------------------------------------------------------
__device__ __forceinline__ uint32_t f2tf32(float f) {
    uint32_t r;
    asm volatile("cvt.rna.tf32.f32 %0, %1;" : "=r"(r) : "f"(f));
    return r;
}

__device__ __forceinline__ void mma_m16n8k8_tf32(
    float& d0, float& d1, float& d2, float& d3,
    uint32_t a0, uint32_t a1, uint32_t a2, uint32_t a3,
    uint32_t b0, uint32_t b1)
{
    asm volatile(
        "mma.sync.aligned.m16n8k8.row.col.f32.tf32.tf32.f32 "
        "{%0,%1,%2,%3}, {%4,%5,%6,%7}, {%8,%9}, {%0,%1,%2,%3};\n"
        : "+f"(d0), "+f"(d1), "+f"(d2), "+f"(d3)
        : "r"(a0), "r"(a1), "r"(a2), "r"(a3), "r"(b0), "r"(b1));
}

// ---------------------------------------------------------------------------
// Generic tiled GEMM body: C[BM,BN] tile of  C = act(A @ W + bias)
//   A : row-major [*, HDIM] (lda = HDIM = 512, K = 512)
//   W : row-major [HDIM, LDB]
//   C : row-major [*, LDB]   (ldc == LDB)
// Template LDB: 512 (GEMM1) or 128 (GEMM2). RELU: fused activation.
// ---------------------------------------------------------------------------
template<bool RELU, int LDB>
__device__ __forceinline__ void gemm_body(
    const float* __restrict__ A,
    const float* __restrict__ W,
    const float* __restrict__ bias,
    float* __restrict__ C)
{
    constexpr int KDIM = HDIM;          // 512
    constexpr int AS_STRIDE = 20;       // 16 k + 4 pad -> conflict-free frag loads
    constexpr int BS_STRIDE = 136;      // 128 n + 8 pad -> conflict-free frag loads

    const int tid  = threadIdx.x;
    const int lane = tid & 31;
    const int warp = tid >> 5;

    const int bm = blockIdx.y * BM;
    const int bn = blockIdx.x * BN;

    __shared__ __align__(16) uint32_t As[BM * AS_STRIDE];   // [row][k] tf32 bits
    __shared__ __align__(16) uint32_t Bs[BK * BS_STRIDE];   // [k][n]   tf32 bits

    // ---- staging thread mapping ----
    // A tile: 128 rows x 16 k. Each thread: rows {ar, ar+64}, 4 consecutive k.
    const int ar = tid >> 2;            // 0..63
    const int ac = (tid & 3) * 4;       // 0,4,8,12
    // B tile: 16 k x 128 n. Each thread: k = bk, n = {bc, bc+64}, 4 consecutive n.
    const int bk = tid >> 4;            // 0..15
    const int bc = (tid & 15) * 4;      // 0..60

    const float* Aptr0 = A + (size_t)(bm + ar) * KDIM + ac;
    const float* Aptr1 = Aptr0 + (size_t)64 * KDIM;
    const float* Bptr  = W + (size_t)bk * LDB + bn + bc;

    // first tile prefetch (global -> regs)
    float4 ra0 = *(const float4*)(Aptr0);
    float4 ra1 = *(const float4*)(Aptr1);
    float4 rb0 = *(const float4*)(Bptr);
    float4 rb1 = *(const float4*)(Bptr + 64);

    // warp tile: 64 (m) x 32 (n); warps arranged 2 x 4
    const int wm = warp >> 2;           // 0..1
    const int wn = warp & 3;            // 0..3
    const int g  = lane >> 2;           // groupID   0..7
    const int t  = lane & 3;            // tid-in-group 0..3

    float acc[4][4][4];
    #pragma unroll
    for (int mi = 0; mi < 4; ++mi)
        #pragma unroll
        for (int ni = 0; ni < 4; ++ni)
            #pragma unroll
            for (int r = 0; r < 4; ++r)
                acc[mi][ni][r] = 0.0f;

    #pragma unroll 1
    for (int kt = 0; kt < KDIM / BK; ++kt) {
        __syncthreads();   // previous compute done before smem overwrite

        // cvt fp32 -> tf32 bits, store to smem
        {
            uint4 p;
            p.x = f2tf32(ra0.x); p.y = f2tf32(ra0.y); p.z = f2tf32(ra0.z); p.w = f2tf32(ra0.w);
            *(uint4*)&As[ar * AS_STRIDE + ac] = p;
            p.x = f2tf32(ra1.x); p.y = f2tf32(ra1.y); p.z = f2tf32(ra1.z); p.w = f2tf32(ra1.w);
            *(uint4*)&As[(ar + 64) * AS_STRIDE + ac] = p;
            p.x = f2tf32(rb0.x); p.y = f2tf32(rb0.y); p.z = f2tf32(rb0.z); p.w = f2tf32(rb0.w);
            *(uint4*)&Bs[bk * BS_STRIDE + bc] = p;
            p.x = f2tf32(rb1.x); p.y = f2tf32(rb1.y); p.z = f2tf32(rb1.z); p.w = f2tf32(rb1.w);
            *(uint4*)&Bs[bk * BS_STRIDE + bc + 64] = p;
        }
        __syncthreads();

        // prefetch next tile while computing this one
        if (kt + 1 < KDIM / BK) {
            const int ko = (kt + 1) * BK;
            ra0 = *(const float4*)(Aptr0 + ko);
            ra1 = *(const float4*)(Aptr1 + ko);
            rb0 = *(const float4*)(Bptr + (size_t)ko * LDB);
            rb1 = *(const float4*)(Bptr + (size_t)ko * LDB + 64);
        }

        // compute: two k8 steps
        #pragma unroll
        for (int k8 = 0; k8 < 2; ++k8) {
            const int kb = k8 * 8;
            uint32_t af[4][4], bf[4][2];
            #pragma unroll
            for (int mi = 0; mi < 4; ++mi) {
                const int r0 = (wm * 64 + mi * 16 + g) * AS_STRIDE;
                af[mi][0] = As[r0 + kb + t];
                af[mi][1] = As[r0 + 8 * AS_STRIDE + kb + t];
                af[mi][2] = As[r0 + kb + t + 4];
                af[mi][3] = As[r0 + 8 * AS_STRIDE + kb + t + 4];
            }
            #pragma unroll
            for (int ni = 0; ni < 4; ++ni) {
                const int cb = wn * 32 + ni * 8 + g;
                bf[ni][0] = Bs[(kb + t) * BS_STRIDE + cb];
                bf[ni][1] = Bs[(kb + t + 4) * BS_STRIDE + cb];
            }
            #pragma unroll
            for (int mi = 0; mi < 4; ++mi)
                #pragma unroll
                for (int ni = 0; ni < 4; ++ni)
                    mma_m16n8k8_tf32(acc[mi][ni][0], acc[mi][ni][1],
                                     acc[mi][ni][2], acc[mi][ni][3],
                                     af[mi][0], af[mi][1], af[mi][2], af[mi][3],
                                     bf[ni][0], bf[ni][1]);
        }
    }

    // ---- epilogue: bias (+relu), write C ----
    #pragma unroll
    for (int mi = 0; mi < 4; ++mi) {
        const int r0g = bm + wm * 64 + mi * 16 + g;
        const int r1g = r0g + 8;
        #pragma unroll
        for (int ni = 0; ni < 4; ++ni) {
            const int c0g = bn + wn * 32 + ni * 8 + t * 2;
            const float bv0 = bias[c0g];
            const float bv1 = bias[c0g + 1];
            float v00 = acc[mi][ni][0] + bv0;
            float v01 = acc[mi][ni][1] + bv1;
            float v10 = acc[mi][ni][2] + bv0;
            float v11 = acc[mi][ni][3] + bv1;
            if (RELU) {
                v00 = fmaxf(v00, 0.0f); v01 = fmaxf(v01, 0.0f);
                v10 = fmaxf(v10, 0.0f); v11 = fmaxf(v11, 0.0f);
            }
            *(float2*)&C[(size_t)r0g * LDB + c0g] = make_float2(v00, v01);
            *(float2*)&C[(size_t)r1g * LDB + c0g] = make_float2(v10, v11);
        }
    }
}

// ---------------------------------------------------------------------------
// GEMM1: H[z] = relu(X @ W1[z] + b1[z]),  z = bank*5 + e
// grid (4, 128, 15)
// ---------------------------------------------------------------------------
__global__ __launch_bounds__(NTHREADS)
void gemm1_kernel(const float* __restrict__ sx,
                  const float* __restrict__ tx0,
                  const float* __restrict__ tx1,
                  const float* __restrict__ sW1,
                  const float* __restrict__ sb1,
                  const float* __restrict__ tW1,
                  const float* __restrict__ tb1)
{
    const int z = blockIdx.z;
    const int bank = z / NEXP;
    const int e = z - bank * NEXP;

    const float* X = (bank == 0) ? sx : ((bank == 1) ? tx0 : tx1);
    const float* W = (bank == 0) ? sW1 + (size_t)e * HDIM * HDIM
                                 : tW1 + ((size_t)(bank - 1) * NEXP + e) * HDIM * HDIM;
    const float* bias = (bank == 0) ? sb1 + (size_t)e * HDIM
                                    : tb1 + ((size_t)(bank - 1) * NEXP + e) * HDIM;
    float* C = g_H + (size_t)z * BATCH * HDIM;

    gemm_body<true, HDIM>(X, W, bias, C);
}

// ---------------------------------------------------------------------------
// GEMM2: O[z] = H[z] @ W2[z] + b2[z]
// grid (1, 128, 15)
// ---------------------------------------------------------------------------
__global__ __launch_bounds__(NTHREADS)
void gemm2_kernel(const float* __restrict__ sW2,
                  const float* __restrict__ sb2,
                  const float* __restrict__ tW2,
                  const float* __restrict__ tb2,
                  float* __restrict__ out)
{
    const int z = blockIdx.z;
    const int bank = z / NEXP;
    const int e = z - bank * NEXP;

    const float* A = g_H + (size_t)z * BATCH * HDIM;
    const float* W = (bank == 0) ? sW2 + (size_t)e * HDIM * ODIM
                                 : tW2 + ((size_t)(bank - 1) * NEXP + e) * HDIM * ODIM;
    const float* bias = (bank == 0) ? sb2 + (size_t)e * ODIM
                                    : tb2 + ((size_t)(bank - 1) * NEXP + e) * ODIM;
    float* C = out + (size_t)z * BATCH * ODIM;

    gemm_body<false, ODIM>(A, W, bias, C);
}

// ---------------------------------------------------------------------------
// Launch
// ---------------------------------------------------------------------------
extern "C" void kernel_launch(void* const* d_in, const int* in_sizes, int n_in,
                              void* d_out, int out_size)
{
    const float* share_x  = (const float*)d_in[0];
    const float* task_x0  = (const float*)d_in[1];
    const float* task_x1  = (const float*)d_in[2];
    const float* share_W1 = (const float*)d_in[3];
    const float* share_b1 = (const float*)d_in[4];
    const float* share_W2 = (const float*)d_in[5];
    const float* share_b2 = (const float*)d_in[6];
    const float* task_W1  = (const float*)d_in[7];
    const float* task_b1  = (const float*)d_in[8];
    const float* task_W2  = (const float*)d_in[9];
    const float* task_b2  = (const float*)d_in[10];
    float* out = (float*)d_out;

    dim3 blk(NTHREADS);
    dim3 g1(HDIM / BN, BATCH / BM, NZ);   // (4, 128, 15)
    dim3 g2(ODIM / BN, BATCH / BM, NZ);   // (1, 128, 15)

    gemm1_kernel<<<g1, blk>>>(share_x, task_x0, task_x1,
                              share_W1, share_b1, task_W1, task_b1);
    gemm2_kernel<<<g2, blk>>>(share_W2, share_b2, task_W2, task_b2, out);
}

// round 3
// speedup vs baseline: 1.0851x; 1.0851x over previous
#include <cuda_runtime.h>
#include <cstdint>
#include <cstddef>

// Problem constants
#define BATCH   16384
#define HDIM    512
#define ODIM    128
#define NEXP    5
#define NZ      15          // 3 banks * 5 experts

// Tiling
#define BM 128
#define BN 128
#define BK 16
#define NTHREADS 256
#define AS_STRIDE 20        // 16 k + 4 pad  -> conflict-free frag loads
#define BS_STRIDE 136       // 128 n + 8 pad -> conflict-free frag loads

// Scratch: H intermediate stored as tf32 bits; pre-converted tf32 weights
__device__ uint32_t g_H  [(size_t)NZ * BATCH * HDIM];
__device__ uint32_t g_W1t[(size_t)NZ * HDIM * HDIM];
__device__ uint32_t g_W2t[(size_t)NZ * HDIM * ODIM];

// ---------------------------------------------------------------------------
// helpers
// ---------------------------------------------------------------------------
__device__ __forceinline__ uint32_t f2tf32(float f) {
    uint32_t r;
    asm("cvt.rna.tf32.f32 %0, %1;" : "=r"(r) : "f"(f));
    return r;
}

__device__ __forceinline__ void cp16(uint32_t smem, const void* gmem) {
    asm volatile("cp.async.cg.shared.global [%0], [%1], 16;\n"
                 :: "r"(smem), "l"(gmem));
}
__device__ __forceinline__ void cp_commit() {
    asm volatile("cp.async.commit_group;\n");
}
__device__ __forceinline__ void cp_wait_all() {
    asm volatile("cp.async.wait_group 0;\n");
}

__device__ __forceinline__ void mma_m16n8k8_tf32(
    float& d0, float& d1, float& d2, float& d3,
    uint32_t a0, uint32_t a1, uint32_t a2, uint32_t a3,
    uint32_t b0, uint32_t b1)
{
    asm volatile(
        "mma.sync.aligned.m16n8k8.row.col.f32.tf32.tf32.f32 "
        "{%0,%1,%2,%3}, {%4,%5,%6,%7}, {%8,%9}, {%0,%1,%2,%3};\n"
        : "+f"(d0), "+f"(d1), "+f"(d2), "+f"(d3)
        : "r"(a0), "r"(a1), "r"(a2), "r"(a3), "r"(b0), "r"(b1));
}

// ---------------------------------------------------------------------------
// Weight pre-conversion: fp32 -> tf32 bits, laid out z-major (z = bank*5+e)
// ---------------------------------------------------------------------------
__global__ void cvt_w_kernel(const float* __restrict__ sW1, const float* __restrict__ tW1,
                             const float* __restrict__ sW2, const float* __restrict__ tW2)
{
    const int i = blockIdx.x * blockDim.x + threadIdx.x;   // float4 index
    const int n1 = NZ * HDIM * HDIM / 4;
    const int n2 = NZ * HDIM * ODIM / 4;
    if (i < n1) {
        const int per = HDIM * HDIM / 4;
        const int z = i / per, r = i - z * per;
        const float4* src = (const float4*)((z < NEXP)
            ? sW1 + (size_t)z * HDIM * HDIM
            : tW1 + (size_t)(z - NEXP) * HDIM * HDIM);
        float4 v = src[r];
        ((uint4*)g_W1t)[i] = make_uint4(f2tf32(v.x), f2tf32(v.y), f2tf32(v.z), f2tf32(v.w));
    } else if (i < n1 + n2) {
        const int j = i - n1;
        const int per = HDIM * ODIM / 4;
        const int z = j / per, r = j - z * per;
        const float4* src = (const float4*)((z < NEXP)
            ? sW2 + (size_t)z * HDIM * ODIM
            : tW2 + (size_t)(z - NEXP) * HDIM * ODIM);
        float4 v = src[r];
        ((uint4*)g_W2t)[j] = make_uint4(f2tf32(v.x), f2tf32(v.y), f2tf32(v.z), f2tf32(v.w));
    }
}

// ---------------------------------------------------------------------------
// Pipelined GEMM body: C[BM,BN] tile of C = act(A @ W + bias)
//   A    : row-major [*, 512]; raw fp32 bits (A_CVT=true) or tf32 bits
//   Wt   : row-major [512, LDB], tf32 bits (pre-converted)
//   Cout : row-major [*, LDB]; tf32 bits (OUT_TF32) or fp32
// 2-stage cp.async double buffer, one __syncthreads per k-tile.
// ---------------------------------------------------------------------------
template<bool RELU, int LDB, bool A_CVT, bool OUT_TF32>
__device__ __forceinline__ void gemm_body(
    const uint32_t* __restrict__ A,
    const uint32_t* __restrict__ Wt,
    const float*    __restrict__ bias,
    uint32_t*       __restrict__ Cout)
{
    constexpr int KDIM = HDIM;

    const int tid  = threadIdx.x;
    const int lane = tid & 31;
    const int warp = tid >> 5;
    const int bm = blockIdx.y * BM;
    const int bn = blockIdx.x * BN;

    __shared__ __align__(16) uint32_t As[2][BM * AS_STRIDE];
    __shared__ __align__(16) uint32_t Bs[2][BK * BS_STRIDE];

    // staging mapping (16B per cp.async, 4 per thread per stage)
    const int ar = tid >> 2;            // 0..63  (rows ar, ar+64)
    const int ac = (tid & 3) * 4;       // 0,4,8,12
    const int bk = tid >> 4;            // 0..15
    const int bc = (tid & 15) * 4;      // 0..60  (cols bc, bc+64)

    const uint32_t* Ap0 = A + (size_t)(bm + ar) * KDIM + ac;
    const uint32_t* Ap1 = Ap0 + (size_t)64 * KDIM;
    const uint32_t* Bp  = Wt + (size_t)bk * LDB + bn + bc;

    uint32_t sa0[2], sa1[2], sb0[2], sb1[2];
    #pragma unroll
    for (int s = 0; s < 2; ++s) {
        sa0[s] = (uint32_t)__cvta_generic_to_shared(&As[s][ar * AS_STRIDE + ac]);
        sa1[s] = (uint32_t)__cvta_generic_to_shared(&As[s][(ar + 64) * AS_STRIDE + ac]);
        sb0[s] = (uint32_t)__cvta_generic_to_shared(&Bs[s][bk * BS_STRIDE + bc]);
        sb1[s] = (uint32_t)__cvta_generic_to_shared(&Bs[s][bk * BS_STRIDE + bc + 64]);
    }

    // warp tile 64x32, warps 2x4
    const int wm = warp >> 2, wn = warp & 3;
    const int g  = lane >> 2, t  = lane & 3;

    float acc[4][4][4] = {};

    // prologue: stage 0
    {
        cp16(sa0[0], Ap0);
        cp16(sa1[0], Ap1);
        cp16(sb0[0], Bp);
        cp16(sb1[0], Bp + 64);
        cp_commit();
    }

    const int NK = KDIM / BK;   // 32
    #pragma unroll 1
    for (int kt = 0; kt < NK; ++kt) {
        const int s = kt & 1;
        cp_wait_all();
        __syncthreads();

        // issue next stage (overlaps with compute below)
        if (kt + 1 < NK) {
            const int ko = (kt + 1) * BK;
            cp16(sa0[s ^ 1], Ap0 + ko);
            cp16(sa1[s ^ 1], Ap1 + ko);
            const uint32_t* b = Bp + (size_t)ko * LDB;
            cp16(sb0[s ^ 1], b);
            cp16(sb1[s ^ 1], b + 64);
            cp_commit();
        }

        // compute this stage: two k8 steps
        #pragma unroll
        for (int k8 = 0; k8 < 2; ++k8) {
            const int kb = k8 * 8;
            uint32_t af[4][4], bf[4][2];
            #pragma unroll
            for (int mi = 0; mi < 4; ++mi) {
                const int r0 = (wm * 64 + mi * 16 + g) * AS_STRIDE;
                uint32_t x0 = As[s][r0 + kb + t];
                uint32_t x1 = As[s][r0 + 8 * AS_STRIDE + kb + t];
                uint32_t x2 = As[s][r0 + kb + t + 4];
                uint32_t x3 = As[s][r0 + 8 * AS_STRIDE + kb + t + 4];
                if (A_CVT) {
                    x0 = f2tf32(__uint_as_float(x0));
                    x1 = f2tf32(__uint_as_float(x1));
                    x2 = f2tf32(__uint_as_float(x2));
                    x3 = f2tf32(__uint_as_float(x3));
                }
                af[mi][0] = x0; af[mi][1] = x1; af[mi][2] = x2; af[mi][3] = x3;
            }
            #pragma unroll
            for (int ni = 0; ni < 4; ++ni) {
                const int cb = wn * 32 + ni * 8 + g;
                bf[ni][0] = Bs[s][(kb + t) * BS_STRIDE + cb];
                bf[ni][1] = Bs[s][(kb + t + 4) * BS_STRIDE + cb];
            }
            #pragma unroll
            for (int mi = 0; mi < 4; ++mi)
                #pragma unroll
                for (int ni = 0; ni < 4; ++ni)
                    mma_m16n8k8_tf32(acc[mi][ni][0], acc[mi][ni][1],
                                     acc[mi][ni][2], acc[mi][ni][3],
                                     af[mi][0], af[mi][1], af[mi][2], af[mi][3],
                                     bf[ni][0], bf[ni][1]);
        }
    }

    // ---- epilogue: bias (+relu), write C ----
    #pragma unroll
    for (int mi = 0; mi < 4; ++mi) {
        const int r0g = bm + wm * 64 + mi * 16 + g;
        const int r1g = r0g + 8;
        #pragma unroll
        for (int ni = 0; ni < 4; ++ni) {
            const int c0g = bn + wn * 32 + ni * 8 + t * 2;
            const float bv0 = bias[c0g];
            const float bv1 = bias[c0g + 1];
            float v00 = acc[mi][ni][0] + bv0;
            float v01 = acc[mi][ni][1] + bv1;
            float v10 = acc[mi][ni][2] + bv0;
            float v11 = acc[mi][ni][3] + bv1;
            if (RELU) {
                v00 = fmaxf(v00, 0.0f); v01 = fmaxf(v01, 0.0f);
                v10 = fmaxf(v10, 0.0f); v11 = fmaxf(v11, 0.0f);
            }
            if (OUT_TF32) {
                *(uint2*)&Cout[(size_t)r0g * LDB + c0g] = make_uint2(f2tf32(v00), f2tf32(v01));
                *(uint2*)&Cout[(size_t)r1g * LDB + c0g] = make_uint2(f2tf32(v10), f2tf32(v11));
            } else {
                *(float2*)&((float*)Cout)[(size_t)r0g * LDB + c0g] = make_float2(v00, v01);
                *(float2*)&((float*)Cout)[(size_t)r1g * LDB + c0g] = make_float2(v10, v11);
            }
        }
    }
}

// ---------------------------------------------------------------------------
// GEMM1: H[z] = tf32(relu(X @ W1[z] + b1[z]))     grid (4, 128, 15)
// ---------------------------------------------------------------------------
__global__ __launch_bounds__(NTHREADS)
void gemm1_kernel(const float* __restrict__ sx,
                  const float* __restrict__ tx0,
                  const float* __restrict__ tx1,
                  const float* __restrict__ sb1,
                  const float* __restrict__ tb1)
{
    const int z = blockIdx.z;
    const int bank = z / NEXP;
    const int e = z - bank * NEXP;

    const float* X = (bank == 0) ? sx : ((bank == 1) ? tx0 : tx1);
    const float* bias = (bank == 0) ? sb1 + (size_t)e * HDIM
                                    : tb1 + ((size_t)(bank - 1) * NEXP + e) * HDIM;
    const uint32_t* Wt = g_W1t + (size_t)z * HDIM * HDIM;
    uint32_t* C = g_H + (size_t)z * BATCH * HDIM;

    gemm_body<true, HDIM, true, true>((const uint32_t*)X, Wt, bias, C);
}

// ---------------------------------------------------------------------------
// GEMM2: O[z] = H[z] @ W2[z] + b2[z]              grid (1, 128, 15)
// ---------------------------------------------------------------------------
__global__ __launch_bounds__(NTHREADS)
void gemm2_kernel(const float* __restrict__ sb2,
                  const float* __restrict__ tb2,
                  float* __restrict__ out)
{
    const int z = blockIdx.z;
    const int bank = z / NEXP;
    const int e = z - bank * NEXP;

    const uint32_t* A  = g_H + (size_t)z * BATCH * HDIM;
    const uint32_t* Wt = g_W2t + (size_t)z * HDIM * ODIM;
    const float* bias = (bank == 0) ? sb2 + (size_t)e * ODIM
                                    : tb2 + ((size_t)(bank - 1) * NEXP + e) * ODIM;

    gemm_body<false, ODIM, false, false>(A, Wt, bias, (uint32_t*)(out + (size_t)z * BATCH * ODIM));
}

// ---------------------------------------------------------------------------
// Launch
// ---------------------------------------------------------------------------
extern "C" void kernel_launch(void* const* d_in, const int* in_sizes, int n_in,
                              void* d_out, int out_size)
{
    const float* share_x  = (const float*)d_in[0];
    const float* task_x0  = (const float*)d_in[1];
    const float* task_x1  = (const float*)d_in[2];
    const float* share_W1 = (const float*)d_in[3];
    const float* share_b1 = (const float*)d_in[4];
    const float* share_W2 = (const float*)d_in[5];
    const float* share_b2 = (const float*)d_in[6];
    const float* task_W1  = (const float*)d_in[7];
    const float* task_b1  = (const float*)d_in[8];
    const float* task_W2  = (const float*)d_in[9];
    const float* task_b2  = (const float*)d_in[10];
    float* out = (float*)d_out;

    // 1) pre-convert weights to tf32 bits
    const int total4 = (NZ * HDIM * HDIM + NZ * HDIM * ODIM) / 4;   // 1,228,800
    cvt_w_kernel<<<(total4 + 255) / 256, 256>>>(share_W1, task_W1, share_W2, task_W2);

    // 2) GEMM1 + 3) GEMM2
    dim3 blk(NTHREADS);
    gemm1_kernel<<<dim3(HDIM / BN, BATCH / BM, NZ), blk>>>(share_x, task_x0, task_x1,
                                                           share_b1, task_b1);
    gemm2_kernel<<<dim3(ODIM / BN, BATCH / BM, NZ), blk>>>(share_b2, task_b2, out);
}

// round 6
// speedup vs baseline: 2.5048x; 2.3083x over previous
#include <cuda_runtime.h>
#include <cuda_fp16.h>
#include <cstdint>
#include <cstddef>

#define BATCH 16384
#define HDIM  512
#define ODIM  128
#define NEXP  5
#define NZ    15

#define BM    128
#define BN    128
#define BK    32             // halfs per k-tile
#define NKT   (HDIM/BK)      // 16
#define STAGES 3
#define NTH   256
#define STAGE_BYTES 16384    // 8KB A + 8KB B (half)

// device scratch (static; allocation-guard-safe)
__device__ __half g_Xh [(size_t)3  * BATCH * HDIM];   // fp16 inputs  [bank][m][k]
__device__ __half g_H  [(size_t)NZ * BATCH * HDIM];   // fp16 hidden  [z][m][k]
__device__ __half g_W1h[(size_t)NZ * HDIM * HDIM];    // fp16 [z][n][k] (transposed)
__device__ __half g_W2h[(size_t)NZ * ODIM * HDIM];    // fp16 [z][n][k] (transposed)

// ---------------------------------------------------------------------------
// helpers
// ---------------------------------------------------------------------------
__device__ __forceinline__ uint32_t smem_u32(const void* p) {
    uint32_t a;
    asm("{ .reg .u64 t; cvta.to.shared.u64 t, %1; cvt.u32.u64 %0, t; }" : "=r"(a) : "l"(p));
    return a;
}
__device__ __forceinline__ void cp16(uint32_t s, const void* g) {
    asm volatile("cp.async.cg.shared.global [%0], [%1], 16;\n" :: "r"(s), "l"(g));
}
__device__ __forceinline__ void cp_commit() { asm volatile("cp.async.commit_group;\n"); }
template<int N> __device__ __forceinline__ void cp_wait() {
    asm volatile("cp.async.wait_group %0;\n" :: "n"(N));
}
__device__ __forceinline__ void ldsm4(uint32_t& d0, uint32_t& d1, uint32_t& d2, uint32_t& d3,
                                      uint32_t a) {
    asm volatile("ldmatrix.sync.aligned.m8n8.x4.shared.b16 {%0,%1,%2,%3}, [%4];"
                 : "=r"(d0), "=r"(d1), "=r"(d2), "=r"(d3) : "r"(a));
}
__device__ __forceinline__ void mma16816(float& d0, float& d1, float& d2, float& d3,
                                         uint32_t a0, uint32_t a1, uint32_t a2, uint32_t a3,
                                         uint32_t b0, uint32_t b1) {
    asm volatile(
        "mma.sync.aligned.m16n8k16.row.col.f32.f16.f16.f32 "
        "{%0,%1,%2,%3}, {%4,%5,%6,%7}, {%8,%9}, {%0,%1,%2,%3};"
        : "+f"(d0), "+f"(d1), "+f"(d2), "+f"(d3)
        : "r"(a0), "r"(a1), "r"(a2), "r"(a3), "r"(b0), "r"(b1));
}
// granule swizzle: row r (0..127), k-granule c (0..3); 16B granules, conflict-free
// for both cp.async stores and 8-consecutive-row ldmatrix phases.
__device__ __forceinline__ uint32_t swoff(int r, int c) {
    return (uint32_t)((r * 4 + (c ^ ((r >> 1) & 3))) * 16);
}

// ---------------------------------------------------------------------------
// conversion kernels
// ---------------------------------------------------------------------------
__global__ void cvt_x_kernel(const float* __restrict__ x0, const float* __restrict__ x1,
                             const float* __restrict__ x2)
{
    const size_t per = (size_t)BATCH * HDIM / 4;
    const size_t i = (size_t)blockIdx.x * blockDim.x + threadIdx.x;
    if (i >= 3 * per) return;
    const int bank = (int)(i / per);
    const size_t r = i - (size_t)bank * per;
    const float4 v = ((const float4*)(bank == 0 ? x0 : bank == 1 ? x1 : x2))[r];
    __half2 h0 = __floats2half2_rn(v.x, v.y);
    __half2 h1 = __floats2half2_rn(v.z, v.w);
    ((uint2*)g_Xh)[i] = make_uint2(*(uint32_t*)&h0, *(uint32_t*)&h1);
}

// transpose + convert: Wt[z][n][k] = half(W[z][k][n])
__global__ void cvt_w_kernel(const float* __restrict__ sW1, const float* __restrict__ tW1,
                             const float* __restrict__ sW2, const float* __restrict__ tW2)
{
    __shared__ float t[32][33];
    int b = blockIdx.x;
    const float* src; __half* dst; int N, n0, k0;
    if (b < NZ * 256) {                      // W1: 16 n-tiles x 16 k-tiles per z
        const int z = b >> 8, r = b & 255;
        n0 = (r >> 4) * 32; k0 = (r & 15) * 32;
        src = (z < NEXP) ? sW1 + (size_t)z * HDIM * HDIM
                         : tW1 + (size_t)(z - NEXP) * HDIM * HDIM;
        dst = g_W1h + (size_t)z * HDIM * HDIM;
        N = HDIM;
    } else {                                 // W2: 16 k-tiles x 4 n-tiles per z
        b -= NZ * 256;
        const int z = b >> 6, r = b & 63;
        k0 = (r >> 2) * 32; n0 = (r & 3) * 32;
        src = (z < NEXP) ? sW2 + (size_t)z * HDIM * ODIM
                         : tW2 + (size_t)(z - NEXP) * HDIM * ODIM;
        dst = g_W2h + (size_t)z * ODIM * HDIM;
        N = ODIM;
    }
    const int tx = threadIdx.x, ty = threadIdx.y;   // (32, 8)
    #pragma unroll
    for (int i = 0; i < 4; ++i)
        t[ty + i * 8][tx] = src[(size_t)(k0 + ty + i * 8) * N + n0 + tx];
    __syncthreads();
    #pragma unroll
    for (int i = 0; i < 4; ++i)
        dst[(size_t)(n0 + ty + i * 8) * HDIM + k0 + tx] = __float2half_rn(t[tx][ty + i * 8]);
}

// ---------------------------------------------------------------------------
// fp16 tensor-core GEMM body: C[BM,BN] tile of C = act(A @ W^T + bias)
//   A : [*, 512] half row-major (K-major)
//   W : [n_total, 512] half row-major (K-major, pre-transposed)
// ---------------------------------------------------------------------------
template<bool RELU, bool OUT_HALF, int LDC>
__device__ __forceinline__ void gemm_body(const __half* __restrict__ A,
                                          const __half* __restrict__ W,
                                          const float*  __restrict__ bias,
                                          void* __restrict__ Cout)
{
    __shared__ __align__(1024) char smem[STAGES * STAGE_BYTES];
    const uint32_t sb = smem_u32(smem);

    const int tid = threadIdx.x, lane = tid & 31, wid = tid >> 5;
    const int wm = wid >> 2, wn = wid & 3;              // warps 2 x 4, tile 64 x 32
    const int bm = blockIdx.y * BM, bn = blockIdx.x * BN;

    // ---- cp.async addressing (2 A + 2 B granules per thread per stage) ----
    const int gr = tid >> 2, gc = tid & 3;              // row 0..63, granule 0..3
    const __half* Ag0 = A + (size_t)(bm + gr) * HDIM + gc * 8;
    const __half* Ag1 = Ag0 + (size_t)64 * HDIM;
    const __half* Bg0 = W + (size_t)(bn + gr) * HDIM + gc * 8;
    const __half* Bg1 = Bg0 + (size_t)64 * HDIM;
    const uint32_t sA0 = swoff(gr, gc),       sA1 = swoff(gr + 64, gc);
    const uint32_t sB0 = 8192 + swoff(gr, gc), sB1 = 8192 + swoff(gr + 64, gc);

    // ---- ldmatrix fragment offsets (stage-relative) ----
    uint32_t aoff[4][2], boff[2][2];
    {
        const int arl = wm * 64 + (lane & 15);
        const int ah  = lane >> 4;
        #pragma unroll
        for (int mi = 0; mi < 4; ++mi)
            #pragma unroll
            for (int k16 = 0; k16 < 2; ++k16)
                aoff[mi][k16] = swoff(arl + mi * 16, k16 * 2 + ah);
        const int nrl = wn * 32 + ((lane >> 4) << 3) + (lane & 7);
        const int bh  = (lane >> 3) & 1;
        #pragma unroll
        for (int p = 0; p < 2; ++p)
            #pragma unroll
            for (int k16 = 0; k16 < 2; ++k16)
                boff[p][k16] = 8192 + swoff(nrl + p * 16, k16 * 2 + bh);
    }

    float acc[4][4][4] = {};

    // ---- prologue: fill STAGES-1 stages ----
    #pragma unroll
    for (int s = 0; s < STAGES - 1; ++s) {
        const int ko = s * BK;
        const uint32_t base = sb + s * STAGE_BYTES;
        cp16(base + sA0, Ag0 + ko); cp16(base + sA1, Ag1 + ko);
        cp16(base + sB0, Bg0 + ko); cp16(base + sB1, Bg1 + ko);
        cp_commit();
    }

    #pragma unroll 1
    for (int kt = 0; kt < NKT; ++kt) {
        const int s = kt % STAGES;
        cp_wait<STAGES - 2>();
        __syncthreads();

        // prefetch stage kt+STAGES-1 (overwrites stage consumed last iter)
        if (kt + STAGES - 1 < NKT) {
            const int ps = (kt + STAGES - 1) % STAGES;
            const int ko = (kt + STAGES - 1) * BK;
            const uint32_t base = sb + ps * STAGE_BYTES;
            cp16(base + sA0, Ag0 + ko); cp16(base + sA1, Ag1 + ko);
            cp16(base + sB0, Bg0 + ko); cp16(base + sB1, Bg1 + ko);
        }
        cp_commit();

        // compute
        const uint32_t base = sb + s * STAGE_BYTES;
        #pragma unroll
        for (int k16 = 0; k16 < 2; ++k16) {
            uint32_t af[4][4], bf[4][2];
            #pragma unroll
            for (int mi = 0; mi < 4; ++mi)
                ldsm4(af[mi][0], af[mi][1], af[mi][2], af[mi][3], base + aoff[mi][k16]);
            #pragma unroll
            for (int p = 0; p < 2; ++p)
                ldsm4(bf[2 * p][0], bf[2 * p][1], bf[2 * p + 1][0], bf[2 * p + 1][1],
                      base + boff[p][k16]);
            #pragma unroll
            for (int mi = 0; mi < 4; ++mi)
                #pragma unroll
                for (int ni = 0; ni < 4; ++ni)
                    mma16816(acc[mi][ni][0], acc[mi][ni][1], acc[mi][ni][2], acc[mi][ni][3],
                             af[mi][0], af[mi][1], af[mi][2], af[mi][3],
                             bf[ni][0], bf[ni][1]);
        }
    }

    // ---- epilogue: bias (+relu), write ----
    const int g = lane >> 2, t = lane & 3;
    #pragma unroll
    for (int mi = 0; mi < 4; ++mi) {
        const int r0g = bm + wm * 64 + mi * 16 + g;
        const int r1g = r0g + 8;
        #pragma unroll
        for (int ni = 0; ni < 4; ++ni) {
            const int c0g = bn + wn * 32 + ni * 8 + t * 2;
            const float bv0 = bias[c0g], bv1 = bias[c0g + 1];
            float v00 = acc[mi][ni][0] + bv0;
            float v01 = acc[mi][ni][1] + bv1;
            float v10 = acc[mi][ni][2] + bv0;
            float v11 = acc[mi][ni][3] + bv1;
            if (RELU) {
                v00 = fmaxf(v00, 0.0f); v01 = fmaxf(v01, 0.0f);
                v10 = fmaxf(v10, 0.0f); v11 = fmaxf(v11, 0.0f);
            }
            if (OUT_HALF) {
                __half2 h0 = __floats2half2_rn(v00, v01);
                __half2 h1 = __floats2half2_rn(v10, v11);
                *(__half2*)&((__half*)Cout)[(size_t)r0g * LDC + c0g] = h0;
                *(__half2*)&((__half*)Cout)[(size_t)r1g * LDC + c0g] = h1;
            } else {
                *(float2*)&((float*)Cout)[(size_t)r0g * LDC + c0g] = make_float2(v00, v01);
                *(float2*)&((float*)Cout)[(size_t)r1g * LDC + c0g] = make_float2(v10, v11);
            }
        }
    }
}

// ---------------------------------------------------------------------------
// kernels
// ---------------------------------------------------------------------------
__global__ __launch_bounds__(NTH, 2)
void gemm1_kernel(const float* __restrict__ sb1, const float* __restrict__ tb1)
{
    const int z = blockIdx.z, bank = z / NEXP, e = z - bank * NEXP;
    const __half* A = g_Xh + (size_t)bank * BATCH * HDIM;
    const __half* W = g_W1h + (size_t)z * HDIM * HDIM;
    const float* bias = (bank == 0) ? sb1 + (size_t)e * HDIM
                                    : tb1 + ((size_t)(bank - 1) * NEXP + e) * HDIM;
    __half* C = g_H + (size_t)z * BATCH * HDIM;
    gemm_body<true, true, HDIM>(A, W, bias, C);
}

__global__ __launch_bounds__(NTH, 2)
void gemm2_kernel(const float* __restrict__ sb2, const float* __restrict__ tb2,
                  float* __restrict__ out)
{
    const int z = blockIdx.z, bank = z / NEXP, e = z - bank * NEXP;
    const __half* A = g_H + (size_t)z * BATCH * HDIM;
    const __half* W = g_W2h + (size_t)z * ODIM * HDIM;
    const float* bias = (bank == 0) ? sb2 + (size_t)e * ODIM
                                    : tb2 + ((size_t)(bank - 1) * NEXP + e) * ODIM;
    gemm_body<false, false, ODIM>(A, W, bias, out + (size_t)z * BATCH * ODIM);
}

// ---------------------------------------------------------------------------
// launch
// ---------------------------------------------------------------------------
extern "C" void kernel_launch(void* const* d_in, const int* in_sizes, int n_in,
                              void* d_out, int out_size)
{
    const float* share_x  = (const float*)d_in[0];
    const float* task_x0  = (const float*)d_in[1];
    const float* task_x1  = (const float*)d_in[2];
    const float* share_W1 = (const float*)d_in[3];
    const float* share_b1 = (const float*)d_in[4];
    const float* share_W2 = (const float*)d_in[5];
    const float* share_b2 = (const float*)d_in[6];
    const float* task_W1  = (const float*)d_in[7];
    const float* task_b1  = (const float*)d_in[8];
    const float* task_W2  = (const float*)d_in[9];
    const float* task_b2  = (const float*)d_in[10];
    float* out = (float*)d_out;

    // 1) convert inputs + transpose/convert weights to fp16
    const size_t nx4 = (size_t)3 * BATCH * HDIM / 4;
    cvt_x_kernel<<<(unsigned)((nx4 + 255) / 256), 256>>>(share_x, task_x0, task_x1);
    cvt_w_kernel<<<NZ * 256 + NZ * 64, dim3(32, 8)>>>(share_W1, task_W1, share_W2, task_W2);

    // 2) GEMMs
    gemm1_kernel<<<dim3(HDIM / BN, BATCH / BM, NZ), NTH>>>(share_b1, task_b1);
    gemm2_kernel<<<dim3(ODIM / BN, BATCH / BM, NZ), NTH>>>(share_b2, task_b2, out);
}